// round 1
// baseline (speedup 1.0000x reference)
#include <cuda_runtime.h>
#include <cstdint>

// Problem constants (fixed by reference setup_inputs)
#define BB   8
#define CC   3
#define OO   8
#define HH   128
#define WW   128
#define KSZ  5
#define HO   124      // H - KS + 1
#define WO   124
#define P25  25

#define TILE_W 32
#define TILE_H 16
#define XT_W  (TILE_W + KSZ - 1)   // 36
#define XT_H  (TILE_H + KSZ - 1)   // 20

// block: (32, 8) -> threadIdx.x = output column within tile, threadIdx.y = o
// grid:  (ceil(WO/32)=4, ceil(HO/16)=8, B*C=24)
__global__ __launch_bounds__(256, 4)
void mnn_kernel(const float* __restrict__ x,
                const float* __restrict__ kh_g,
                const float* __restrict__ km_g,
                float* __restrict__ out)
{
    __shared__ float sx[XT_H][XT_W];

    const int tx  = threadIdx.x;          // 0..31
    const int o   = threadIdx.y;          // 0..7
    const int wo0 = blockIdx.x * TILE_W;
    const int ho0 = blockIdx.y * TILE_H;
    const int bc  = blockIdx.z;           // b*C + c
    const int b   = bc / CC;
    const int c   = bc % CC;

    // ---- stage x tile into shared (cooperative, all 256 threads) ----
    const float* __restrict__ xb = x + (size_t)(b * CC + c) * HH * WW;
    const int tid = o * 32 + tx;
    #pragma unroll
    for (int i = tid; i < XT_H * XT_W; i += 256) {
        const int rr = i / XT_W;
        const int cc2 = i % XT_W;
        const int gr = ho0 + rr;
        const int gc = wo0 + cc2;
        sx[rr][cc2] = (gr < HH && gc < WW) ? xb[gr * WW + gc] : 0.0f;
    }

    // ---- weights for this (o, c) into registers ----
    float kh[P25], km[P25];
    {
        const float* __restrict__ khp = kh_g + (size_t)(o * CC + c) * P25;
        const float* __restrict__ kmp = km_g + (size_t)(o * CC + c) * P25;
        #pragma unroll
        for (int p = 0; p < P25; ++p) {
            kh[p] = __ldg(khp + p);
            km[p] = __ldg(kmp + p);
        }
    }
    __syncthreads();

    const int wo = wo0 + tx;
    const bool colok = (wo < WO);
    float* __restrict__ outp =
        out + ((size_t)(b * OO * CC + o * CC + c)) * HO * WO;

    #pragma unroll
    for (int r = 0; r < TILE_H; ++r) {
        const int ho = ho0 + r;
        if (ho >= HO) break;

        float hit  =  3.0e38f;
        float miss = -3.0e38f;
        #pragma unroll
        for (int u = 0; u < KSZ; ++u) {
            #pragma unroll
            for (int v = 0; v < KSZ; ++v) {
                const float t = sx[r + u][tx + v];
                hit  = fminf(hit,  t - kh[u * KSZ + v]);
                miss = fmaxf(miss, t - km[u * KSZ + v]);
            }
        }
        if (colok) outp[(size_t)ho * WO + wo] = hit - miss;
    }
}

extern "C" void kernel_launch(void* const* d_in, const int* in_sizes, int n_in,
                              void* d_out, int out_size)
{
    const float* x     = (const float*)d_in[0];
    const float* K_hit = (const float*)d_in[1];
    const float* K_mis = (const float*)d_in[2];
    float* out = (float*)d_out;

    dim3 grid((WO + TILE_W - 1) / TILE_W,   // 4
              (HO + TILE_H - 1) / TILE_H,   // 8
              BB * CC);                     // 24
    dim3 block(32, 8);
    mnn_kernel<<<grid, block>>>(x, K_hit, K_mis, out);
}

// round 2
// speedup vs baseline: 1.4975x; 1.4975x over previous
#include <cuda_runtime.h>
#include <cstdint>

#define CC   3
#define OO   8
#define HH   128
#define WW   128
#define KSZ  5
#define HO   124
#define WO   124
#define P25  25

#define TILE_W 32
#define TILE_H 31                 // 124 = 4 * 31, all tiles full
#define XT_W  (TILE_W + KSZ - 1)  // 36
#define XT_H  (TILE_H + KSZ - 1)  // 35

// Per-row compute: window w[slot*5+v] (slot = xrow % 5), phase J = r % 5.
// Returns (hit, miss). All indices compile-time -> arrays stay in registers.
template<int J>
__device__ __forceinline__ float2 row_compute(const float* __restrict__ w,
                                              const float* __restrict__ khn,
                                              const float* __restrict__ kmn)
{
    float hu[5], mu[5];
#pragma unroll
    for (int u = 0; u < 5; ++u) {
        const int s = ((J + u) % 5) * 5;
        float h = w[s + 0] + khn[u * 5 + 0];
        float m = w[s + 0] + kmn[u * 5 + 0];
#pragma unroll
        for (int v = 1; v < 5; ++v) {
            h = fminf(h, w[s + v] + khn[u * 5 + v]);
            m = fmaxf(m, w[s + v] + kmn[u * 5 + v]);
        }
        hu[u] = h; mu[u] = m;
    }
    float hit = fminf(fminf(fminf(hu[0], hu[1]), fminf(hu[2], hu[3])), hu[4]);
    float mis = fmaxf(fmaxf(fmaxf(mu[0], mu[1]), fmaxf(mu[2], mu[3])), mu[4]);
    return make_float2(hit, mis);
}

// Load new x row (local row index = phase J + 4 within current chunk base)
// into ring slot (J+4)%5.
#define ROW_STEP(J)                                                          \
    do {                                                                     \
        const float* __restrict__ rp = sxb + ((J) + 4) * XT_W;               \
        _Pragma("unroll")                                                    \
        for (int v = 0; v < 5; ++v) w[(((J) + 4) % 5) * 5 + v] = rp[v];      \
        float2 hm = row_compute<(J)>(w, khn, kmn);                           \
        if (colok) *op = hm.x - hm.y;                                        \
        op += WO;                                                            \
    } while (0)

__global__ __launch_bounds__(256, 3)
void mnn_kernel(const float* __restrict__ x,
                const float* __restrict__ kh_g,
                const float* __restrict__ km_g,
                float* __restrict__ out)
{
    __shared__ float sx[XT_H][XT_W];

    const int tx  = threadIdx.x;          // 0..31  (output column in tile)
    const int o   = threadIdx.y;          // 0..7   (output channel)
    const int wo0 = blockIdx.x * TILE_W;
    const int ho0 = blockIdx.y * TILE_H;
    const int bc  = blockIdx.z;           // b*C + c
    const int b   = bc / CC;
    const int c   = bc % CC;

    // ---- stage x tile (35 x 36) into shared ----
    const float* __restrict__ xb = x + (size_t)bc * HH * WW;
    const int tid = o * 32 + tx;
    for (int i = tid; i < XT_H * XT_W; i += 256) {
        const int rr  = i / XT_W;
        const int cc2 = i % XT_W;
        const int gc  = wo0 + cc2;
        // rows always in-bounds (ho0 <= 93, rr <= 34); cols need a guard
        sx[rr][cc2] = (gc < WW) ? xb[(ho0 + rr) * WW + gc] : 0.0f;
    }

    // ---- negated weights into registers (sub == add of negated) ----
    float khn[P25], kmn[P25];
    {
        const float* __restrict__ khp = kh_g + (size_t)(o * CC + c) * P25;
        const float* __restrict__ kmp = km_g + (size_t)(o * CC + c) * P25;
#pragma unroll
        for (int p = 0; p < P25; ++p) {
            khn[p] = -__ldg(khp + p);
            kmn[p] = -__ldg(kmp + p);
        }
    }
    __syncthreads();

    // ---- prologue: x rows 0..3 into ring slots 0..3 ----
    float w[25];
#pragma unroll
    for (int i = 0; i < 4; ++i)
#pragma unroll
        for (int v = 0; v < 5; ++v)
            w[i * 5 + v] = sx[i][tx + v];

    const bool colok = (wo0 + tx) < WO;
    float* __restrict__ op =
        out + ((size_t)(b * OO * CC + o * CC + c)) * HO * WO
            + (size_t)ho0 * WO + wo0 + tx;

    // sxb points at &sx[chunk_base_row][tx]; advances 5 rows per chunk
    const float* __restrict__ sxb = &sx[0][tx];

    // 6 chunks x 5 rows = rows 0..29
    for (int rc = 0; rc < 6; ++rc) {
        ROW_STEP(0);
        ROW_STEP(1);
        ROW_STEP(2);
        ROW_STEP(3);
        ROW_STEP(4);
        sxb += 5 * XT_W;
    }
    // tail row 30 (phase 0): sxb now at local row 30
    ROW_STEP(0);
}

extern "C" void kernel_launch(void* const* d_in, const int* in_sizes, int n_in,
                              void* d_out, int out_size)
{
    const float* x     = (const float*)d_in[0];
    const float* K_hit = (const float*)d_in[1];
    const float* K_mis = (const float*)d_in[2];
    float* out = (float*)d_out;

    dim3 grid((WO + TILE_W - 1) / TILE_W,   // 4
              (HO + TILE_H - 1) / TILE_H,   // 4
              8 * CC);                      // 24  -> 384 blocks, single wave
    dim3 block(32, 8);
    mnn_kernel<<<grid, block>>>(x, K_hit, K_mis, out);
}

// round 3
// speedup vs baseline: 1.6761x; 1.1193x over previous
#include <cuda_runtime.h>
#include <cstdint>

#define CC   3
#define OO   8
#define HH   128
#define WW   128
#define HO   124
#define WO   124
#define P25  25

#define TILE_W 32
#define XT_W   36      // staged input cols (32 + 4 halo)
#define SROW   72      // splatted floats per staged row (2 * XT_W)
#define XT_H   46      // staged rows (42-row tile + 4 halo)

// Packed fp32x2 add: one FADD2 computes (x + khn, x + kmn) for hit & miss.
__device__ __forceinline__ void fadd2(unsigned long long a, unsigned long long b,
                                      float& lo, float& hi)
{
    asm("{\n\t.reg .b64 t;\n\tadd.rn.f32x2 t, %2, %3;\n\tmov.b64 {%0, %1}, t;\n\t}"
        : "=f"(lo), "=f"(hi) : "l"(a), "l"(b));
}

// One output row. Ring w[slot*5+v] holds splatted (x,x) pairs, slot = row%5.
// J = phase of this output row; all indices compile-time -> registers.
template<int J>
__device__ __forceinline__ float2 row_compute(const unsigned long long* __restrict__ w,
                                              const unsigned long long* __restrict__ kp)
{
    float hu[5], mu[5];
#pragma unroll
    for (int u = 0; u < 5; ++u) {
        const int s = ((J + u) % 5) * 5;
        fadd2(w[s], kp[u * 5], hu[u], mu[u]);
#pragma unroll
        for (int v = 1; v < 5; ++v) {
            float lo, hi;
            fadd2(w[s + v], kp[u * 5 + v], lo, hi);
            hu[u] = fminf(hu[u], lo);
            mu[u] = fmaxf(mu[u], hi);
        }
    }
    const float hit = fminf(fminf(fminf(hu[0], hu[1]), fminf(hu[2], hu[3])), hu[4]);
    const float mis = fmaxf(fmaxf(fmaxf(mu[0], mu[1]), fmaxf(mu[2], mu[3])), mu[4]);
    return make_float2(hit, mis);
}

// Load the new row (local row rbase+J+4) into ring slot (J+4)%5, compute, store.
#define ROW_STEP(J)                                                              \
    do {                                                                         \
        const float* nr = sx2 + (rbase + (J) + 4) * SROW + 2 * tx;               \
        _Pragma("unroll")                                                        \
        for (int v = 0; v < 5; ++v)                                              \
            w[(((J) + 4) % 5) * 5 + v] =                                         \
                *(const unsigned long long*)(nr + 2 * v);                        \
        const float2 hm = row_compute<(J)>(w, kp);                               \
        if (colok) *op = hm.x - hm.y;                                            \
        op += WO;                                                                \
    } while (0)

__global__ __launch_bounds__(256, 2)
void mnn_kernel(const float* __restrict__ x,
                const float* __restrict__ kh_g,
                const float* __restrict__ km_g,
                float* __restrict__ out)
{
    __shared__ float sx2[XT_H * SROW];   // splatted tile: 46 x 72 floats

    const int tx  = threadIdx.x;          // 0..31  output column in tile
    const int o   = threadIdx.y;          // 0..7   output channel
    const int wo0 = blockIdx.x * TILE_W;
    const int ho0 = blockIdx.y * 42;      // y-tiles: 42, 42, 40 rows
    const int bc  = blockIdx.z;           // b*C + c
    const int b   = bc / CC;
    const int c   = bc % CC;
    const int tid = o * 32 + tx;

    // ---- stage x tile into shared, pre-splatted: sx2[r][2j]=sx2[r][2j+1]=x ----
    const float* __restrict__ xb = x + (size_t)bc * HH * WW;
    for (int i = tid; i < XT_H * XT_W; i += 256) {
        const int rr  = i / XT_W;
        const int cc2 = i % XT_W;
        const int gr  = ho0 + rr;
        const int gc  = wo0 + cc2;
        const float v = (gr < HH && gc < WW) ? xb[gr * WW + gc] : 0.0f;
        *(float2*)&sx2[rr * SROW + 2 * cc2] = make_float2(v, v);
    }

    // ---- weights packed as (-K_hit, -K_miss) 64-bit pairs ----
    unsigned long long kp[P25];
    {
        const float* __restrict__ khp = kh_g + (size_t)(o * CC + c) * P25;
        const float* __restrict__ kmp = km_g + (size_t)(o * CC + c) * P25;
#pragma unroll
        for (int p = 0; p < P25; ++p) {
            const float a  = -__ldg(khp + p);
            const float b2 = -__ldg(kmp + p);
            asm("mov.b64 %0, {%1, %2};" : "=l"(kp[p]) : "f"(a), "f"(b2));
        }
    }
    __syncthreads();

    // ---- ring prologue: local rows 0..3 into slots 0..3 ----
    unsigned long long w[P25];
#pragma unroll
    for (int i = 0; i < 4; ++i)
#pragma unroll
        for (int v = 0; v < 5; ++v)
            w[i * 5 + v] =
                *(const unsigned long long*)(sx2 + i * SROW + 2 * (tx + v));

    const bool colok = (wo0 + tx) < WO;
    float* __restrict__ op =
        out + ((size_t)(b * OO * CC + o * CC + c)) * HO * WO
            + (size_t)ho0 * WO + wo0 + tx;

    // ---- 8 chunks x 5 rows = rows 0..39 (no guards needed) ----
    int rbase = 0;
    for (int rc = 0; rc < 8; ++rc) {
        ROW_STEP(0);
        ROW_STEP(1);
        ROW_STEP(2);
        ROW_STEP(3);
        ROW_STEP(4);
        rbase += 5;
    }
    // tail rows 40,41 only for the two 42-row y-tiles
    if (blockIdx.y < 2) {
        ROW_STEP(0);
        ROW_STEP(1);
    }
}

extern "C" void kernel_launch(void* const* d_in, const int* in_sizes, int n_in,
                              void* d_out, int out_size)
{
    const float* x     = (const float*)d_in[0];
    const float* K_hit = (const float*)d_in[1];
    const float* K_mis = (const float*)d_in[2];
    float* out = (float*)d_out;

    dim3 grid(4, 3, OO * CC);   // 288 blocks -> ~97% single-wave balance at 2/SM
    dim3 block(32, 8);
    mnn_kernel<<<grid, block>>>(x, K_hit, K_mis, out);
}